// round 16
// baseline (speedup 1.0000x reference)
#include <cuda_runtime.h>

#define NPIX 786432
#define KER 9
#define CIN 16
#define COUT 16
#define TPB 128

typedef unsigned long long u64;

__device__ __forceinline__ u64 pack2(float lo, float hi) {
    u64 r; asm("mov.b64 %0, {%1, %2};" : "=l"(r) : "f"(lo), "f"(hi)); return r;
}
__device__ __forceinline__ void unpack2(u64 v, float& lo, float& hi) {
    asm("mov.b64 {%0, %1}, %2;" : "=f"(lo), "=f"(hi) : "l"(v));
}
__device__ __forceinline__ void fma2(u64& d, u64 a, u64 b) {
    asm("fma.rn.f32x2 %0, %1, %2, %0;" : "+l"(d) : "l"(a), "l"(b));
}
__device__ __forceinline__ void add2(u64& d, u64 a) {
    asm("add.rn.f32x2 %0, %0, %1;" : "+l"(d) : "l"(a));
}

// One batch per launch. f32x2 lanes pair adjacent CHANNELS (not batches):
// acc[o] = (sum over even c, sum over odd c); x/w float4s reinterpret as two
// u64 pairs with no duplication ALU at all. Final horizontal add after the
// lane reduce.
__global__ __launch_bounds__(TPB, 8) void healpix_conv_batch_kernel(
    const float* __restrict__ xb,     // (NPIX, CIN)   one batch
    const int*   __restrict__ nb,     // (NPIX, KER)
    const float* __restrict__ w,      // (COUT, KER, CIN)
    const float* __restrict__ bias,   // (COUT,)
    float*       __restrict__ yb)     // (NPIX, COUT)  one batch
{
    // w scalar f32, layout [k][o][c] (9 KB): lane q reads float4 at c=q*4.
    __shared__ float ws[KER * COUT * CIN];

    const int tid = threadIdx.x;
    for (int i = tid; i < KER * COUT * CIN; i += TPB) {
        const int c = i & 15;
        const int o = (i >> 4) & 15;
        const int k = i >> 8;
        ws[i] = w[(o * KER + k) * CIN + c];
    }
    __syncthreads();

    const int lane = tid & 31;
    const int warp = tid >> 5;
    const int q = lane & 3;        // channel-quarter owned by this lane
    const int g = lane >> 2;       // pixel group (0..7)
    const int n = (blockIdx.x * (TPB / 32) + warp) * 8 + g;   // this thread's pixel

    u64 acc[COUT];                 // (even-c partial, odd-c partial)
    #pragma unroll
    for (int o = 0; o < COUT; o++) acc[o] = 0ULL;

    const float* xq = xb + q * 4;  // quarter-row base

    // prefetch all 9 neighbour indices (4 lanes of a group load the same
    // value -> dedup; 32 B distinct per warp-instruction)
    int ids[KER];
    {
        const int* nbp = nb + (size_t)n * KER;
        #pragma unroll
        for (int k = 0; k < KER; k++) ids[k] = __ldg(nbp + k);
    }

    // software pipeline depth 1 on the gathered row
    float4 a_cur;
    bool v_cur;
    {
        v_cur = (ids[0] < NPIX);
        const int s = v_cur ? ids[0] : 0;
        a_cur = __ldg((const float4*)(xq + (size_t)s * CIN));
    }

    #pragma unroll 1
    for (int k = 0; k < KER; k++) {
        float4 a_n;
        bool v_n = false;
        if (k + 1 < KER) {
            v_n = (ids[k + 1] < NPIX);
            const int s = v_n ? ids[k + 1] : 0;
            a_n = __ldg((const float4*)(xq + (size_t)s * CIN));
        }

        // two channel-pairs from the gathered quarter (zeroed for pad row)
        const u64 xp0 = v_cur ? pack2(a_cur.x, a_cur.y) : 0ULL;
        const u64 xp1 = v_cur ? pack2(a_cur.z, a_cur.w) : 0ULL;

        const float* wk = ws + k * COUT * CIN + q * 4;
        #pragma unroll
        for (int o = 0; o < COUT; o++) {
            const float4 wv = *(const float4*)(wk + o * CIN);
            fma2(acc[o], xp0, pack2(wv.x, wv.y));
            fma2(acc[o], xp1, pack2(wv.z, wv.w));
        }

        a_cur = a_n; v_cur = v_n;
    }

    // all-reduce partial sums across the 4 lanes of each pixel group
    #pragma unroll
    for (int o = 0; o < COUT; o++) {
        u64 t = __shfl_xor_sync(0xffffffffu, acc[o], 1);
        add2(acc[o], t);
        t = __shfl_xor_sync(0xffffffffu, acc[o], 2);
        add2(acc[o], t);
    }

    // lane q keeps o in [4q, 4q+4): horizontal add (even+odd) + bias, store
    const float4 b4 = *(const float4*)(bias + q * 4);
    float lo0, hi0, lo1, hi1, lo2, hi2, lo3, hi3;
    unpack2(acc[q * 4 + 0], lo0, hi0);
    unpack2(acc[q * 4 + 1], lo1, hi1);
    unpack2(acc[q * 4 + 2], lo2, hi2);
    unpack2(acc[q * 4 + 3], lo3, hi3);
    float4 out = make_float4(lo0 + hi0 + b4.x, lo1 + hi1 + b4.y,
                             lo2 + hi2 + b4.z, lo3 + hi3 + b4.w);
    *(float4*)(yb + (size_t)n * COUT + q * 4) = out;
}

extern "C" void kernel_launch(void* const* d_in, const int* in_sizes, int n_in,
                              void* d_out, int out_size) {
    const float* x    = (const float*)d_in[0];
    const int*   nb   = (const int*)d_in[1];
    const float* w    = (const float*)d_in[2];
    const float* bias = (const float*)d_in[3];
    float*       y    = (float*)d_out;

    // 128 threads = 4 warps = 32 pixels per block
    const int blocks = NPIX / 32;   // 24576

    // Two sequential launches, one per batch: each kernel's gather working
    // set is 50 MB -> L2-resident -> ~250cyc gather latency, minimal DRAM.
    healpix_conv_batch_kernel<<<blocks, TPB>>>(
        x, nb, w, bias, y);
    healpix_conv_batch_kernel<<<blocks, TPB>>>(
        x + (size_t)NPIX * CIN, nb, w, bias, y + (size_t)NPIX * COUT);
}